// round 9
// baseline (speedup 1.0000x reference)
#include <cuda_runtime.h>
#include <math.h>

#define B_ 4
#define C_ 128
#define T_ 32
#define H_ 24
#define W_ 24
#define M_ 3
#define HW_ (H_*W_)               // 576
#define NPER (B_*C_*T_*HW_)       // 9437184 elements per output tensor

// Scratch (device globals; no allocation allowed)
__device__ float g_qg[B_*T_*C_];     // [b][t][c]  pooled q
__device__ float g_h [B_*T_*C_];     // [b][t][c]  GELU(pre_w @ qg + pre_b)
__device__ float g_alpha[B_*M_*T_];  // [b][m][t]  softmax mixture weights

// ---------------------------------------------------------------------------
// Kernel 1: spatial mean pool of q. One WARP per (b,c,t) slice.
// 576 floats = 144 float4; lane loads f4 at lane, +32, +64, +96, (+128 if <16).
// ---------------------------------------------------------------------------
__global__ __launch_bounds__(256) void pool_kernel(const float4* __restrict__ q4) {
    int w = threadIdx.x >> 5, lane = threadIdx.x & 31;
    int idx = blockIdx.x * 8 + w;          // b*C*T + c*T + t
    const float4* p = q4 + (size_t)idx * 144;
    float4 a = p[lane], b4 = p[lane + 32], c4 = p[lane + 64], d4 = p[lane + 96];
    float s = a.x + a.y + a.z + a.w + b4.x + b4.y + b4.z + b4.w
            + c4.x + c4.y + c4.z + c4.w + d4.x + d4.y + d4.z + d4.w;
    if (lane < 16) {
        float4 e = p[lane + 128];
        s += e.x + e.y + e.z + e.w;
    }
    #pragma unroll
    for (int o = 16; o; o >>= 1) s += __shfl_down_sync(0xffffffffu, s, o);
    if (lane == 0) {
        int t = idx % T_, c = (idx / T_) % C_, b = idx / (T_ * C_);
        g_qg[(b * T_ + t) * C_ + c] = s * (1.0f / HW_);
    }
}

// ---------------------------------------------------------------------------
// Kernel 2: h = GELU(pre_w @ qg + pre_b). grid (B, 4): each block does 8 t's.
// thread = output channel o.
// ---------------------------------------------------------------------------
__global__ __launch_bounds__(128) void mixpre_kernel(const float* __restrict__ pre_w,
                                                     const float* __restrict__ pre_b) {
    int b = blockIdx.x, tg = blockIdx.y, tid = threadIdx.x;
    __shared__ float sq[8 * C_];
    #pragma unroll
    for (int tt = 0; tt < 8; ++tt)
        sq[tt * C_ + tid] = g_qg[(b * T_ + tg * 8 + tt) * C_ + tid];
    __syncthreads();
    float acc[8];
    float pb = pre_b[tid];
    #pragma unroll
    for (int tt = 0; tt < 8; ++tt) acc[tt] = pb;
    #pragma unroll 4
    for (int c = 0; c < C_; ++c) {
        float wv = pre_w[tid * C_ + c];
        #pragma unroll
        for (int tt = 0; tt < 8; ++tt) acc[tt] = fmaf(wv, sq[tt * C_ + c], acc[tt]);
    }
    #pragma unroll
    for (int tt = 0; tt < 8; ++tt) {
        float x = acc[tt];
        g_h[(b * T_ + tg * 8 + tt) * C_ + tid] =
            0.5f * x * (1.0f + erff(x * 0.70710678118654752440f));
    }
}

// ---------------------------------------------------------------------------
// Kernel 3: causal conv1d C->M over T + softmax -> alpha[b,m,t]. grid B_.
// ---------------------------------------------------------------------------
__global__ __launch_bounds__(96) void alpha_kernel(const float* __restrict__ mix_w,
                                                   const float* __restrict__ mix_b) {
    int b = blockIdx.x, tid = threadIdx.x;
    __shared__ float lg[M_ * T_];
    {
        int m = tid >> 5, t = tid & 31;
        float a = mix_b[m];
        #pragma unroll
        for (int j = 0; j < 3; ++j) {
            int tt = t - 2 + j;
            if (tt >= 0) {
                const float* hp = g_h + (b * T_ + tt) * C_;
                const float* wp = mix_w + m * C_ * 3 + j;
                #pragma unroll 8
                for (int c = 0; c < C_; ++c) a = fmaf(wp[c * 3], hp[c], a);
            }
        }
        lg[m * T_ + t] = a;
    }
    __syncthreads();
    if (tid < T_) {
        int t = tid;
        float l0 = lg[t], l1 = lg[T_ + t], l2 = lg[2 * T_ + t];
        float mx = fmaxf(l0, fmaxf(l1, l2));
        float e0 = expf(l0 - mx), e1 = expf(l1 - mx), e2 = expf(l2 - mx);
        float inv = 1.f / (e0 + e1 + e2);
        g_alpha[(b * M_ + 0) * T_ + t] = e0 * inv;
        g_alpha[(b * M_ + 1) * T_ + t] = e1 * inv;
        g_alpha[(b * M_ + 2) * T_ + t] = e2 * inv;
    }
}

// ---------------------------------------------------------------------------
// Kernel 4: fused mixture depthwise causal 3D conv for BOTH k and v.
// Per-thread tile: 2 rows x 4 cols x 2 timesteps, both tensors.
// Effective weights stored as padded float4 groups: wf[to][tensor][d][dh][4]
// so each tap-triple is ONE LDS.128 broadcast (was 6 scalar LDS).
// ---------------------------------------------------------------------------
#define TT    8
#define RS    28       // padded row stride (floats)
#define SLICE (26*RS)  // 728 floats per padded slice
#define WFSZ  144      // 2 to * 2 tensors * 9 (d,dh) * 4 (dw padded)

__global__ __launch_bounds__(72) void conv_kernel(
    const float* __restrict__ kin, const float* __restrict__ vin,
    const float* __restrict__ Wk,  const float* __restrict__ Wv,
    float* __restrict__ out) {
    __shared__ float sm[8 * SLICE + WFSZ];  // 4 k slices, 4 v slices, weights
    float* wf = sm + 8 * SLICE;             // 16B-aligned (5824 % 4 == 0)

    int t0 = blockIdx.x * TT;
    int c = blockIdx.y, b = blockIdx.z;
    int tid = threadIdx.x;
    int hi = tid / 6, seg = tid % 6;
    int h0 = hi * 2, w0 = seg * 4;
    int lrow = tid / 3, lcol = (tid % 3) * 8;   // loader mapping: 8 floats each

    size_t bc = (size_t)b * C_ + c;
    const float* kbase = kin + bc * T_ * HW_;
    const float* vbase = vin + bc * T_ * HW_;
    float* okbase = out + bc * T_ * HW_;
    float* ovbase = out + (size_t)NPER + bc * T_ * HW_;
    const float* Wkc = Wk + c * 27;
    const float* Wvc = Wv + c * 27;

    // zero all slices (borders + temporal zero padding), vectorized
    for (int i = tid; i < (8 * SLICE) / 4; i += 72)
        ((float4*)sm)[i] = make_float4(0.f, 0.f, 0.f, 0.f);

    __syncthreads();   // zeros fully visible before any data is stored

    // prologue: slices t0-2, t0-1
    #pragma unroll
    for (int s = 0; s < 2; ++s) {
        int tt = t0 - 2 + s;
        if (tt >= 0) {
            int slot = tt & 3;
            const float* gk = kbase + (size_t)tt * HW_ + tid * 8;
            const float* gv = vbase + (size_t)tt * HW_ + tid * 8;
            float4 ka = ((const float4*)gk)[0], kb2 = ((const float4*)gk)[1];
            float4 va = ((const float4*)gv)[0], vb2 = ((const float4*)gv)[1];
            float* dk = sm + slot * SLICE + (lrow + 1) * RS + lcol + 1;
            float* dv = sm + (4 + slot) * SLICE + (lrow + 1) * RS + lcol + 1;
            dk[0]=ka.x; dk[1]=ka.y; dk[2]=ka.z; dk[3]=ka.w;
            dk[4]=kb2.x; dk[5]=kb2.y; dk[6]=kb2.z; dk[7]=kb2.w;
            dv[0]=va.x; dv[1]=va.y; dv[2]=va.z; dv[3]=va.w;
            dv[4]=vb2.x; dv[5]=vb2.y; dv[6]=vb2.z; dv[7]=vb2.w;
        }
    }

    #pragma unroll 1
    for (int p = 0; p < TT / 2; ++p) {
        int t = t0 + 2 * p;
        __syncthreads();   // previous pair's reads done before slot overwrite
        // load slices t, t+1 (always in range)
        #pragma unroll
        for (int s = 0; s < 2; ++s) {
            int tt = t + s;
            int slot = tt & 3;
            const float* gk = kbase + (size_t)tt * HW_ + tid * 8;
            const float* gv = vbase + (size_t)tt * HW_ + tid * 8;
            float4 ka = ((const float4*)gk)[0], kb2 = ((const float4*)gk)[1];
            float4 va = ((const float4*)gv)[0], vb2 = ((const float4*)gv)[1];
            float* dk = sm + slot * SLICE + (lrow + 1) * RS + lcol + 1;
            float* dv = sm + (4 + slot) * SLICE + (lrow + 1) * RS + lcol + 1;
            dk[0]=ka.x; dk[1]=ka.y; dk[2]=ka.z; dk[3]=ka.w;
            dk[4]=kb2.x; dk[5]=kb2.y; dk[6]=kb2.z; dk[7]=kb2.w;
            dv[0]=va.x; dv[1]=va.y; dv[2]=va.z; dv[3]=va.w;
            dv[4]=vb2.x; dv[5]=vb2.y; dv[6]=vb2.z; dv[7]=vb2.w;
        }
        // effective weights, padded layout: wf[(((to*2+tensor)*9)+d*3+dh)*4 + dw]
        for (int idx = tid; idx < WFSZ; idx += 72) {
            int g = idx >> 2, dw = idx & 3;
            int to = g / 18, r2 = g % 18;
            int tensor = r2 / 9, qd = r2 % 9;
            int j = qd * 3 + dw;                // d*9? no: qd=(d*3+dh) -> j=d*9+dh*3+dw
            int d = qd / 3, dh = qd % 3;
            j = d * 9 + dh * 3 + dw;
            float val = 0.f;
            if (dw < 3) {
                int tt = t + to;
                float a0 = g_alpha[(b * M_ + 0) * T_ + tt];
                float a1 = g_alpha[(b * M_ + 1) * T_ + tt];
                float a2 = g_alpha[(b * M_ + 2) * T_ + tt];
                const float* Wc = tensor ? Wvc : Wkc;
                val = a0 * Wc[j] + a1 * Wc[C_ * 27 + j] + a2 * Wc[2 * C_ * 27 + j];
            }
            wf[idx] = val;
        }
        __syncthreads();

        float ak[2][2][4], av[2][2][4];
        #pragma unroll
        for (int i = 0; i < 2; ++i)
            #pragma unroll
            for (int r = 0; r < 2; ++r)
                #pragma unroll
                for (int wi = 0; wi < 4; ++wi) { ak[i][r][wi] = 0.f; av[i][r][wi] = 0.f; }

        #pragma unroll
        for (int si = 0; si < 4; ++si) {
            int slot = (t - 2 + si) & 3;  // -2&3=2, -1&3=3: correct mod-4
            const float* skb = sm + slot * SLICE;
            const float* svb = sm + (4 + slot) * SLICE;
            #pragma unroll
            for (int ri = 0; ri < 4; ++ri) {
                const float* rkp = skb + (h0 + ri) * RS + w0;  // aligned float4
                float4 f0 = ((const float4*)rkp)[0], f1 = ((const float4*)rkp)[1];
                float rowk[8] = {f0.x,f0.y,f0.z,f0.w,f1.x,f1.y,f1.z,f1.w};
                const float* rvp = svb + (h0 + ri) * RS + w0;
                float4 g0 = ((const float4*)rvp)[0], g1 = ((const float4*)rvp)[1];
                float rowv[8] = {g0.x,g0.y,g0.z,g0.w,g1.x,g1.y,g1.z,g1.w};
                #pragma unroll
                for (int to = 0; to < 2; ++to) {
                    int d = si - to;
                    if (d < 0 || d > 2) continue;       // compile-time after unroll
                    #pragma unroll
                    for (int r = 0; r < 2; ++r) {
                        int dh = ri - r;
                        if (dh < 0 || dh > 2) continue; // compile-time after unroll
                        float4 wk4 = *(const float4*)&wf[((to * 2 + 0) * 9 + d * 3 + dh) * 4];
                        float4 wv4 = *(const float4*)&wf[((to * 2 + 1) * 9 + d * 3 + dh) * 4];
                        float wkk[3] = {wk4.x, wk4.y, wk4.z};
                        float wvv[3] = {wv4.x, wv4.y, wv4.z};
                        #pragma unroll
                        for (int dw = 0; dw < 3; ++dw) {
                            #pragma unroll
                            for (int wi = 0; wi < 4; ++wi) {
                                ak[to][r][wi] = fmaf(wkk[dw], rowk[wi + dw], ak[to][r][wi]);
                                av[to][r][wi] = fmaf(wvv[dw], rowv[wi + dw], av[to][r][wi]);
                            }
                        }
                    }
                }
            }
        }
        #pragma unroll
        for (int to = 0; to < 2; ++to)
            #pragma unroll
            for (int r = 0; r < 2; ++r) {
                size_t off = (size_t)(t + to) * HW_ + (h0 + r) * W_ + w0;
                ((float4*)(okbase + off))[0] =
                    make_float4(ak[to][r][0], ak[to][r][1], ak[to][r][2], ak[to][r][3]);
                ((float4*)(ovbase + off))[0] =
                    make_float4(av[to][r][0], av[to][r][1], av[to][r][2], av[to][r][3]);
            }
    }
}

// ---------------------------------------------------------------------------
// Launch. inputs: 0=q 1=k 2=v 3=Wk 4=Wv 5=pre_w 6=pre_b 7=mix_w 8=mix_b
// ---------------------------------------------------------------------------
extern "C" void kernel_launch(void* const* d_in, const int* in_sizes, int n_in,
                              void* d_out, int out_size) {
    const float* q     = (const float*)d_in[0];
    const float* k     = (const float*)d_in[1];
    const float* v     = (const float*)d_in[2];
    const float* Wk    = (const float*)d_in[3];
    const float* Wv    = (const float*)d_in[4];
    const float* pre_w = (const float*)d_in[5];
    const float* pre_b = (const float*)d_in[6];
    const float* mix_w = (const float*)d_in[7];
    const float* mix_b = (const float*)d_in[8];
    float* out = (float*)d_out;

    pool_kernel<<<(B_ * C_ * T_) / 8, 256>>>((const float4*)q);
    {
        dim3 g(B_, 4);
        mixpre_kernel<<<g, 128>>>(pre_w, pre_b);
    }
    alpha_kernel<<<B_, 96>>>(mix_w, mix_b);
    {
        dim3 g(T_ / TT, C_, B_);
        conv_kernel<<<g, 72>>>(k, v, Wk, Wv, out);
    }
}

// round 10
// speedup vs baseline: 1.0961x; 1.0961x over previous
#include <cuda_runtime.h>
#include <math.h>

#define B_ 4
#define C_ 128
#define T_ 32
#define H_ 24
#define W_ 24
#define M_ 3
#define HW_ (H_*W_)               // 576
#define NPER (B_*C_*T_*HW_)       // 9437184 elements per output tensor

// Scratch (device globals; no allocation allowed)
__device__ float g_qg[B_*T_*C_];     // [b][t][c]  pooled q
__device__ float g_alpha[B_*M_*T_];  // [b][m][t]  softmax mixture weights

// ---------------------------------------------------------------------------
// Kernel 1: spatial mean pool of q. One WARP per (b,c,t) slice.
// 576 floats = 144 float4; lane loads f4 at lane, +32, +64, +96, (+128 if <16).
// ---------------------------------------------------------------------------
__global__ __launch_bounds__(256) void pool_kernel(const float4* __restrict__ q4) {
    int w = threadIdx.x >> 5, lane = threadIdx.x & 31;
    int idx = blockIdx.x * 8 + w;          // b*C*T + c*T + t
    const float4* p = q4 + (size_t)idx * 144;
    float4 a = p[lane], b4 = p[lane + 32], c4 = p[lane + 64], d4 = p[lane + 96];
    float s = a.x + a.y + a.z + a.w + b4.x + b4.y + b4.z + b4.w
            + c4.x + c4.y + c4.z + c4.w + d4.x + d4.y + d4.z + d4.w;
    if (lane < 16) {
        float4 e = p[lane + 128];
        s += e.x + e.y + e.z + e.w;
    }
    #pragma unroll
    for (int o = 16; o; o >>= 1) s += __shfl_down_sync(0xffffffffu, s, o);
    if (lane == 0) {
        int t = idx % T_, c = (idx / T_) % C_, b = idx / (T_ * C_);
        g_qg[(b * T_ + t) * C_ + c] = s * (1.0f / HW_);
    }
}

// ---------------------------------------------------------------------------
// Kernel 2 (fused): per batch b: h = GELU(pre_w @ qg + pre_b) for all t (kept
// in smem), then causal conv1d C->M + softmax -> alpha[b,m,t]. grid = B_.
// (The R4 fused version — splitting this into two kernels cost ~30us.)
// ---------------------------------------------------------------------------
__global__ __launch_bounds__(128) void mix_kernel(const float* __restrict__ pre_w,
                                                  const float* __restrict__ pre_b,
                                                  const float* __restrict__ mix_w,
                                                  const float* __restrict__ mix_b) {
    int b = blockIdx.x, tid = threadIdx.x;
    __shared__ float sq[T_ * C_];
    __shared__ float sh[T_ * C_];
    __shared__ float lg[M_ * T_];

    #pragma unroll
    for (int t = 0; t < T_; ++t) sq[t * C_ + tid] = g_qg[(b * T_ + t) * C_ + tid];
    __syncthreads();

    float acc[T_];
    float pb = pre_b[tid];
    #pragma unroll
    for (int t = 0; t < T_; ++t) acc[t] = pb;
    for (int c = 0; c < C_; ++c) {
        float wv = pre_w[tid * C_ + c];
        #pragma unroll
        for (int t = 0; t < T_; ++t) acc[t] = fmaf(wv, sq[t * C_ + c], acc[t]);
    }
    #pragma unroll
    for (int t = 0; t < T_; ++t) {
        float x = acc[t];
        sh[t * C_ + tid] = 0.5f * x * (1.0f + erff(x * 0.70710678118654752440f));
    }
    __syncthreads();

    if (tid < 96) {
        int m = tid >> 5, t = tid & 31;
        float a = mix_b[m];
        #pragma unroll
        for (int j = 0; j < 3; ++j) {
            int tt = t - 2 + j;
            if (tt >= 0) {
                const float* hp = sh + tt * C_;
                const float* wp = mix_w + m * C_ * 3 + j;
                #pragma unroll 8
                for (int c = 0; c < C_; ++c) a = fmaf(wp[c * 3], hp[c], a);
            }
        }
        lg[m * T_ + t] = a;
    }
    __syncthreads();
    if (tid < T_) {
        int t = tid;
        float l0 = lg[t], l1 = lg[T_ + t], l2 = lg[2 * T_ + t];
        float mx = fmaxf(l0, fmaxf(l1, l2));
        float e0 = expf(l0 - mx), e1 = expf(l1 - mx), e2 = expf(l2 - mx);
        float inv = 1.f / (e0 + e1 + e2);
        g_alpha[(b * M_ + 0) * T_ + t] = e0 * inv;
        g_alpha[(b * M_ + 1) * T_ + t] = e1 * inv;
        g_alpha[(b * M_ + 2) * T_ + t] = e2 * inv;
    }
}

// ---------------------------------------------------------------------------
// Kernel 3: fused mixture depthwise causal 3D conv for BOTH k and v.
// TWO channels per block (144 threads = 2 x 72-thread groups): idle-lane
// fraction 25% -> 10%. Per-thread tile: 2 rows x 4 cols x 2 timesteps.
// Weight quads hoisted per (si,to) before the ri loop: 72 -> 36 broadcast
// LDS.128 per thread-iteration.
// ---------------------------------------------------------------------------
#define TT    8
#define RS    28       // padded row stride (floats)
#define SLICE (26*RS)  // 728 floats per padded slice
#define WFSZ  144      // 2 to * 2 tensors * 9 (d,dh) * 4 (dw padded)

__global__ __launch_bounds__(144) void conv_kernel(
    const float* __restrict__ kin, const float* __restrict__ vin,
    const float* __restrict__ Wk,  const float* __restrict__ Wv,
    float* __restrict__ out) {
    __shared__ float sm[16 * SLICE + 2 * WFSZ];  // [ch][8 slices] + [ch][wf]
    int tid = threadIdx.x;
    int ch = tid / 72, lt = tid % 72;
    float* base = sm + ch * 8 * SLICE;
    float* wf = sm + 16 * SLICE + ch * WFSZ;     // 16B-aligned

    int t0 = blockIdx.x * TT;
    int c = blockIdx.y * 2 + ch, b = blockIdx.z;
    int hi = lt / 6, seg = lt % 6;
    int h0 = hi * 2, w0 = seg * 4;
    int lrow = lt / 3, lcol = (lt % 3) * 8;      // loader mapping: 8 floats each

    size_t bc = (size_t)b * C_ + c;
    const float* kbase = kin + bc * T_ * HW_;
    const float* vbase = vin + bc * T_ * HW_;
    float* okbase = out + bc * T_ * HW_;
    float* ovbase = out + (size_t)NPER + bc * T_ * HW_;
    const float* Wkc = Wk + c * 27;
    const float* Wvc = Wv + c * 27;

    // zero all slices (borders + temporal zero padding), vectorized
    for (int i = tid; i < (16 * SLICE) / 4; i += 144)
        ((float4*)sm)[i] = make_float4(0.f, 0.f, 0.f, 0.f);

    __syncthreads();   // zeros fully visible before any data is stored

    // prologue: slices t0-2, t0-1
    #pragma unroll
    for (int s = 0; s < 2; ++s) {
        int tt = t0 - 2 + s;
        if (tt >= 0) {
            int slot = tt & 3;
            const float* gk = kbase + (size_t)tt * HW_ + lt * 8;
            const float* gv = vbase + (size_t)tt * HW_ + lt * 8;
            float4 ka = ((const float4*)gk)[0], kb2 = ((const float4*)gk)[1];
            float4 va = ((const float4*)gv)[0], vb2 = ((const float4*)gv)[1];
            float* dk = base + slot * SLICE + (lrow + 1) * RS + lcol + 1;
            float* dv = base + (4 + slot) * SLICE + (lrow + 1) * RS + lcol + 1;
            dk[0]=ka.x; dk[1]=ka.y; dk[2]=ka.z; dk[3]=ka.w;
            dk[4]=kb2.x; dk[5]=kb2.y; dk[6]=kb2.z; dk[7]=kb2.w;
            dv[0]=va.x; dv[1]=va.y; dv[2]=va.z; dv[3]=va.w;
            dv[4]=vb2.x; dv[5]=vb2.y; dv[6]=vb2.z; dv[7]=vb2.w;
        }
    }

    #pragma unroll 1
    for (int p = 0; p < TT / 2; ++p) {
        int t = t0 + 2 * p;
        __syncthreads();   // previous pair's reads done before slot overwrite
        // load slices t, t+1 (always in range)
        #pragma unroll
        for (int s = 0; s < 2; ++s) {
            int tt = t + s;
            int slot = tt & 3;
            const float* gk = kbase + (size_t)tt * HW_ + lt * 8;
            const float* gv = vbase + (size_t)tt * HW_ + lt * 8;
            float4 ka = ((const float4*)gk)[0], kb2 = ((const float4*)gk)[1];
            float4 va = ((const float4*)gv)[0], vb2 = ((const float4*)gv)[1];
            float* dk = base + slot * SLICE + (lrow + 1) * RS + lcol + 1;
            float* dv = base + (4 + slot) * SLICE + (lrow + 1) * RS + lcol + 1;
            dk[0]=ka.x; dk[1]=ka.y; dk[2]=ka.z; dk[3]=ka.w;
            dk[4]=kb2.x; dk[5]=kb2.y; dk[6]=kb2.z; dk[7]=kb2.w;
            dv[0]=va.x; dv[1]=va.y; dv[2]=va.z; dv[3]=va.w;
            dv[4]=vb2.x; dv[5]=vb2.y; dv[6]=vb2.z; dv[7]=vb2.w;
        }
        // effective weights, padded layout: wf[((to*2+tensor)*9 + d*3+dh)*4 + dw]
        for (int idx = lt; idx < WFSZ; idx += 72) {
            int g = idx >> 2, dw = idx & 3;
            int to = g / 18, r2 = g % 18;
            int tensor = r2 / 9, qd = r2 % 9;
            int d = qd / 3, dh = qd % 3;
            int j = d * 9 + dh * 3 + dw;
            float val = 0.f;
            if (dw < 3) {
                int tt = t + to;
                float a0 = g_alpha[(b * M_ + 0) * T_ + tt];
                float a1 = g_alpha[(b * M_ + 1) * T_ + tt];
                float a2 = g_alpha[(b * M_ + 2) * T_ + tt];
                const float* Wc = tensor ? Wvc : Wkc;
                val = a0 * Wc[j] + a1 * Wc[C_ * 27 + j] + a2 * Wc[2 * C_ * 27 + j];
            }
            wf[idx] = val;
        }
        __syncthreads();

        float ak[2][2][4], av[2][2][4];
        #pragma unroll
        for (int i = 0; i < 2; ++i)
            #pragma unroll
            for (int r = 0; r < 2; ++r)
                #pragma unroll
                for (int wi = 0; wi < 4; ++wi) { ak[i][r][wi] = 0.f; av[i][r][wi] = 0.f; }

        #pragma unroll
        for (int si = 0; si < 4; ++si) {
            int slot = (t - 2 + si) & 3;  // -2&3=2, -1&3=3: correct mod-4
            const float* skb = base + slot * SLICE;
            const float* svb = base + (4 + slot) * SLICE;

            // hoisted weight quads for this si: [to][dh], only valid to's used
            float4 wk4[2][3], wv4[2][3];
            #pragma unroll
            for (int to = 0; to < 2; ++to) {
                int d = si - to;
                if (d < 0 || d > 2) continue;       // compile-time after unroll
                #pragma unroll
                for (int dh = 0; dh < 3; ++dh) {
                    wk4[to][dh] = *(const float4*)&wf[((to * 2 + 0) * 9 + d * 3 + dh) * 4];
                    wv4[to][dh] = *(const float4*)&wf[((to * 2 + 1) * 9 + d * 3 + dh) * 4];
                }
            }

            #pragma unroll
            for (int ri = 0; ri < 4; ++ri) {
                const float* rkp = skb + (h0 + ri) * RS + w0;  // aligned float4
                float4 f0 = ((const float4*)rkp)[0], f1 = ((const float4*)rkp)[1];
                float rowk[8] = {f0.x,f0.y,f0.z,f0.w,f1.x,f1.y,f1.z,f1.w};
                const float* rvp = svb + (h0 + ri) * RS + w0;
                float4 g0 = ((const float4*)rvp)[0], g1 = ((const float4*)rvp)[1];
                float rowv[8] = {g0.x,g0.y,g0.z,g0.w,g1.x,g1.y,g1.z,g1.w};
                #pragma unroll
                for (int to = 0; to < 2; ++to) {
                    int d = si - to;
                    if (d < 0 || d > 2) continue;       // compile-time after unroll
                    #pragma unroll
                    for (int r = 0; r < 2; ++r) {
                        int dh = ri - r;
                        if (dh < 0 || dh > 2) continue; // compile-time after unroll
                        float wkk[3] = {wk4[to][dh].x, wk4[to][dh].y, wk4[to][dh].z};
                        float wvv[3] = {wv4[to][dh].x, wv4[to][dh].y, wv4[to][dh].z};
                        #pragma unroll
                        for (int dw = 0; dw < 3; ++dw) {
                            #pragma unroll
                            for (int wi = 0; wi < 4; ++wi) {
                                ak[to][r][wi] = fmaf(wkk[dw], rowk[wi + dw], ak[to][r][wi]);
                                av[to][r][wi] = fmaf(wvv[dw], rowv[wi + dw], av[to][r][wi]);
                            }
                        }
                    }
                }
            }
        }
        #pragma unroll
        for (int to = 0; to < 2; ++to)
            #pragma unroll
            for (int r = 0; r < 2; ++r) {
                size_t off = (size_t)(t + to) * HW_ + (h0 + r) * W_ + w0;
                ((float4*)(okbase + off))[0] =
                    make_float4(ak[to][r][0], ak[to][r][1], ak[to][r][2], ak[to][r][3]);
                ((float4*)(ovbase + off))[0] =
                    make_float4(av[to][r][0], av[to][r][1], av[to][r][2], av[to][r][3]);
            }
    }
}

// ---------------------------------------------------------------------------
// Launch. inputs: 0=q 1=k 2=v 3=Wk 4=Wv 5=pre_w 6=pre_b 7=mix_w 8=mix_b
// ---------------------------------------------------------------------------
extern "C" void kernel_launch(void* const* d_in, const int* in_sizes, int n_in,
                              void* d_out, int out_size) {
    const float* q     = (const float*)d_in[0];
    const float* k     = (const float*)d_in[1];
    const float* v     = (const float*)d_in[2];
    const float* Wk    = (const float*)d_in[3];
    const float* Wv    = (const float*)d_in[4];
    const float* pre_w = (const float*)d_in[5];
    const float* pre_b = (const float*)d_in[6];
    const float* mix_w = (const float*)d_in[7];
    const float* mix_b = (const float*)d_in[8];
    float* out = (float*)d_out;

    pool_kernel<<<(B_ * C_ * T_) / 8, 256>>>((const float4*)q);
    mix_kernel<<<B_, 128>>>(pre_w, pre_b, mix_w, mix_b);
    {
        dim3 g(T_ / TT, C_ / 2, B_);
        conv_kernel<<<g, 144>>>(k, v, Wk, Wv, out);
    }
}